// round 4
// baseline (speedup 1.0000x reference)
#include <cuda_runtime.h>
#include <cstdint>

// ---------------------------------------------------------------------------
// CausalSelfAttention: B=4, S=2048, D=1024, fp32, causal softmax (scale 1/32)
// Staged: [round inputs] -> [proj x3] -> [scores lower-tri] -> [softmax] -> [PV]
// All GEMMs tf32 mma.sync m16n8k8. All operands are pre-rounded to tf32 at
// production time, so GEMM inner loops do NO cvt (pure LDS + HMMA).
// ---------------------------------------------------------------------------

#define BATCH 4
#define SEQ   2048
#define DIM   1024
#define NQT   (SEQ / 128)
#define NTRI  (NQT * (NQT + 1) / 2)   // 136 lower-tri tiles

// Scratch (static __device__ globals: allocation-free per harness rules)
__device__ float g_X [(size_t)BATCH * SEQ * DIM];   // tf32-rounded x
__device__ float g_Wq[(size_t)DIM * DIM];
__device__ float g_Wk[(size_t)DIM * DIM];
__device__ float g_Wv[(size_t)DIM * DIM];
__device__ float g_Q [(size_t)BATCH * SEQ * DIM];
__device__ float g_K [(size_t)BATCH * SEQ * DIM];
__device__ float g_V [(size_t)BATCH * SEQ * DIM];
__device__ float g_S [(size_t)BATCH * SEQ * SEQ];

// ---------------------------------------------------------------------------
__device__ __forceinline__ uint32_t f2tf32(float f) {
    uint32_t u;
    asm("cvt.rna.tf32.f32 %0, %1;" : "=r"(u) : "f"(f));
    return u;
}
__device__ __forceinline__ float roundtf(float f) {
    return __uint_as_float(f2tf32(f));
}

__device__ __forceinline__ void mma_tf32(float* d, const uint32_t* a,
                                         const uint32_t* b, const float* c) {
    asm volatile(
        "mma.sync.aligned.m16n8k8.row.col.f32.tf32.tf32.f32 "
        "{%0,%1,%2,%3}, {%4,%5,%6,%7}, {%8,%9}, {%10,%11,%12,%13};\n"
        : "=f"(d[0]), "=f"(d[1]), "=f"(d[2]), "=f"(d[3])
        : "r"(a[0]), "r"(a[1]), "r"(a[2]), "r"(a[3]),
          "r"(b[0]), "r"(b[1]),
          "f"(c[0]), "f"(c[1]), "f"(c[2]), "f"(c[3]));
}

__device__ __forceinline__ void cpa16(void* smem, const void* g) {
    uint32_t s = (uint32_t)__cvta_generic_to_shared(smem);
    asm volatile("cp.async.cg.shared.global [%0], [%1], 16;\n" :: "r"(s), "l"(g));
}
#define CP_COMMIT() asm volatile("cp.async.commit_group;\n")
#define CP_WAIT(n)  asm volatile("cp.async.wait_group %0;\n" :: "n"(n))

// ---------------------------------------------------------------------------
// 128x128 tile GEMM core. Operands in smem are ALREADY tf32-rounded floats.
//   MODE 0: B stored [n][k] (k contig)  -> C = A @ B^T
//   MODE 1: B stored [k][n] (n contig)  -> C = A @ B
// ROUND 1: round C to tf32 on store (for tensors feeding later GEMMs).
// ---------------------------------------------------------------------------
template <int MODE, int ROUND>
__device__ __forceinline__ void gemm_core(const float* __restrict__ A,
                                          const float* __restrict__ Bm,
                                          float* __restrict__ C,
                                          int lda, int ldb, int ldc,
                                          int kIters, int row0, int col0) {
    constexpr int BM = 128, BN = 128, BK = 16;
    constexpr int BROWS = (MODE == 0) ? BN : BK;
    constexpr int BCOLS = (MODE == 0) ? BK : BN;
    constexpr int BPAD  = (MODE == 0) ? 4  : 8;

    __shared__ float As[2][BM][BK + 4];
    __shared__ float Bs[2][BROWS][BCOLS + BPAD];

    const int tid  = threadIdx.x;
    const int warp = tid >> 5;
    const int lane = tid & 31;
    const int wm   = (warp >> 2) * 64;
    const int wn   = (warp & 3) * 32;
    const int gid  = lane >> 2;
    const int tig  = lane & 3;

    float acc[4][4][4];
#pragma unroll
    for (int i = 0; i < 4; i++)
#pragma unroll
        for (int j = 0; j < 4; j++)
#pragma unroll
            for (int r = 0; r < 4; r++) acc[i][j][r] = 0.f;

    auto loadA = [&](int kt, int buf) {
#pragma unroll
        for (int i = 0; i < 2; i++) {
            int f = tid + i * 256;
            int r = f >> 2, q = f & 3;
            cpa16(&As[buf][r][q * 4],
                  &A[(size_t)(row0 + r) * lda + kt * BK + q * 4]);
        }
    };
    auto loadB = [&](int kt, int buf) {
        if (MODE == 0) {
#pragma unroll
            for (int i = 0; i < 2; i++) {
                int f = tid + i * 256;
                int r = f >> 2, q = f & 3;
                cpa16(&Bs[buf][r][q * 4],
                      &Bm[(size_t)(col0 + r) * ldb + kt * BK + q * 4]);
            }
        } else {
#pragma unroll
            for (int i = 0; i < 2; i++) {
                int f = tid + i * 256;
                int r = f >> 5, q = f & 31;
                cpa16(&Bs[buf][r][q * 4],
                      &Bm[(size_t)(kt * BK + r) * ldb + col0 + q * 4]);
            }
        }
    };

    loadA(0, 0);
    loadB(0, 0);
    CP_COMMIT();

    int buf = 0;
    for (int kt = 0; kt < kIters; kt++) {
        if (kt + 1 < kIters) {
            loadA(kt + 1, buf ^ 1);
            loadB(kt + 1, buf ^ 1);
            CP_COMMIT();
            CP_WAIT(1);
        } else {
            CP_WAIT(0);
        }
        __syncthreads();

#pragma unroll
        for (int ks = 0; ks < 2; ks++) {
            const int kk = ks * 8;
            uint32_t af[4][4];
#pragma unroll
            for (int mf = 0; mf < 4; mf++) {
                int r = wm + mf * 16 + gid;
                af[mf][0] = __float_as_uint(As[buf][r][kk + tig]);
                af[mf][1] = __float_as_uint(As[buf][r + 8][kk + tig]);
                af[mf][2] = __float_as_uint(As[buf][r][kk + tig + 4]);
                af[mf][3] = __float_as_uint(As[buf][r + 8][kk + tig + 4]);
            }
            uint32_t bf[4][2];
#pragma unroll
            for (int nf = 0; nf < 4; nf++) {
                int n = wn + nf * 8 + gid;
                if (MODE == 0) {
                    bf[nf][0] = __float_as_uint(Bs[buf][n][kk + tig]);
                    bf[nf][1] = __float_as_uint(Bs[buf][n][kk + tig + 4]);
                } else {
                    bf[nf][0] = __float_as_uint(Bs[buf][kk + tig][n]);
                    bf[nf][1] = __float_as_uint(Bs[buf][kk + tig + 4][n]);
                }
            }
#pragma unroll
            for (int mf = 0; mf < 4; mf++)
#pragma unroll
                for (int nf = 0; nf < 4; nf++)
                    mma_tf32(acc[mf][nf], af[mf], bf[nf], acc[mf][nf]);
        }
        __syncthreads();
        buf ^= 1;
    }

#pragma unroll
    for (int mf = 0; mf < 4; mf++) {
#pragma unroll
        for (int nf = 0; nf < 4; nf++) {
            int r = row0 + wm + mf * 16 + gid;
            int c = col0 + wn + nf * 8 + tig * 2;
            float v0 = acc[mf][nf][0], v1 = acc[mf][nf][1];
            float v2 = acc[mf][nf][2], v3 = acc[mf][nf][3];
            if (ROUND) { v0 = roundtf(v0); v1 = roundtf(v1);
                         v2 = roundtf(v2); v3 = roundtf(v3); }
            C[(size_t)r * ldc + c]           = v0;
            C[(size_t)r * ldc + c + 1]       = v1;
            C[(size_t)(r + 8) * ldc + c]     = v2;
            C[(size_t)(r + 8) * ldc + c + 1] = v3;
        }
    }
}

// ---------------------------------------------------------------------------
// kernels
// ---------------------------------------------------------------------------

// Pre-round x and the 3 weight matrices to tf32 (vectorized float4).
__global__ __launch_bounds__(256) void round_kernel(const float4* __restrict__ x,
                                                    const float4* __restrict__ wq,
                                                    const float4* __restrict__ wk,
                                                    const float4* __restrict__ wv) {
    const float4* src;
    float4* dst;
    int n4;
    switch (blockIdx.y) {
        case 0: src = x;  dst = (float4*)g_X;  n4 = BATCH * SEQ * DIM / 4; break;
        case 1: src = wq; dst = (float4*)g_Wq; n4 = DIM * DIM / 4; break;
        case 2: src = wk; dst = (float4*)g_Wk; n4 = DIM * DIM / 4; break;
        default: src = wv; dst = (float4*)g_Wv; n4 = DIM * DIM / 4; break;
    }
    for (int i = blockIdx.x * 256 + threadIdx.x; i < n4; i += gridDim.x * 256) {
        float4 v = src[i];
        v.x = roundtf(v.x); v.y = roundtf(v.y);
        v.z = roundtf(v.z); v.w = roundtf(v.w);
        dst[i] = v;
    }
}

__global__ __launch_bounds__(256) void proj_kernel() {
    const float* W = (blockIdx.z == 0) ? g_Wq : (blockIdx.z == 1) ? g_Wk : g_Wv;
    float* O = (blockIdx.z == 0) ? g_Q : (blockIdx.z == 1) ? g_K : g_V;
    gemm_core<0, 1>(g_X, W, O, DIM, DIM, DIM, DIM / 16,
                    blockIdx.y * 128, blockIdx.x * 128);
}

__device__ __forceinline__ void tri_decode(int t, int& qt, int& kt) {
    int q = (int)((sqrtf(8.0f * t + 1.0f) - 1.0f) * 0.5f);
    while ((q + 1) * (q + 2) / 2 <= t) q++;
    while (q * (q + 1) / 2 > t) q--;
    qt = q;
    kt = t - q * (q + 1) / 2;
}

__global__ __launch_bounds__(256) void scores_kernel() {
    int qt, kt;
    tri_decode(blockIdx.x, qt, kt);
    int b = blockIdx.z;
    const float* Qp = g_Q + (size_t)b * SEQ * DIM;
    const float* Kp = g_K + (size_t)b * SEQ * DIM;
    float* Sp = g_S + (size_t)b * SEQ * SEQ;
    gemm_core<0, 0>(Qp, Kp, Sp, DIM, DIM, SEQ, DIM / 16, qt * 128, kt * 128);
}

__global__ __launch_bounds__(256) void softmax_kernel() {
    const int row = blockIdx.x;
    const int b = row / SEQ, q = row % SEQ;
    float* p = g_S + (size_t)b * SEQ * SEQ + (size_t)q * SEQ;
    const int len  = q + 1;
    const int kend = ((q / 128) + 1) * 128;
    const float scale = 0.03125f;  // 1/sqrt(1024)

    __shared__ float red[8];
    __shared__ float red2[8];

    float vals[8];
    int cnt = 0;
    float m = -1e30f;
    for (int i = threadIdx.x; i < len; i += 256) {
        float v = p[i];
        vals[cnt++] = v;
        m = fmaxf(m, v);
    }
#pragma unroll
    for (int o = 16; o; o >>= 1) m = fmaxf(m, __shfl_xor_sync(~0u, m, o));
    if ((threadIdx.x & 31) == 0) red[threadIdx.x >> 5] = m;
    __syncthreads();
    m = red[0];
#pragma unroll
    for (int i = 1; i < 8; i++) m = fmaxf(m, red[i]);

    float s = 0.f;
#pragma unroll 8
    for (int j = 0; j < cnt; j++) {
        float e = __expf(scale * (vals[j] - m));
        vals[j] = e;
        s += e;
    }
#pragma unroll
    for (int o = 16; o; o >>= 1) s += __shfl_xor_sync(~0u, s, o);
    if ((threadIdx.x & 31) == 0) red2[threadIdx.x >> 5] = s;
    __syncthreads();
    s = 0.f;
#pragma unroll
    for (int i = 0; i < 8; i++) s += red2[i];
    const float inv = 1.0f / s;

    // write back tf32-rounded probs + zero tail to tile boundary
    cnt = 0;
    for (int i = threadIdx.x; i < len; i += 256)
        p[i] = roundtf(vals[cnt++] * inv);
    for (int i = len + threadIdx.x; i < kend; i += 256) p[i] = 0.f;
}

__global__ __launch_bounds__(256) void pv_kernel(float* __restrict__ out) {
    int qt = blockIdx.y, et = blockIdx.x, b = blockIdx.z;
    const float* P = g_S + (size_t)b * SEQ * SEQ;
    const float* V = g_V + (size_t)b * SEQ * DIM;
    float* O = out + (size_t)b * SEQ * DIM;
    gemm_core<1, 0>(P, V, O, SEQ, DIM, DIM, (qt + 1) * 8, qt * 128, et * 128);
}

// ---------------------------------------------------------------------------
extern "C" void kernel_launch(void* const* d_in, const int* in_sizes, int n_in,
                              void* d_out, int out_size) {
    int xi = 0;
    for (int i = 0; i < n_in; i++)
        if (in_sizes[i] == BATCH * SEQ * DIM) { xi = i; break; }
    const float* x = (const float*)d_in[xi];
    const float* w[3];
    int wi = 0;
    for (int i = 0; i < n_in && wi < 3; i++)
        if (i != xi) w[wi++] = (const float*)d_in[i];
    float* out = (float*)d_out;

    round_kernel<<<dim3(512, 4), 256>>>((const float4*)x, (const float4*)w[0],
                                        (const float4*)w[1], (const float4*)w[2]);
    proj_kernel<<<dim3(8, 64, 3), 256>>>();
    scores_kernel<<<dim3(NTRI, 1, 4), 256>>>();
    softmax_kernel<<<BATCH * SEQ, 256>>>();
    pv_kernel<<<dim3(8, 16, 4), 256>>>(out);
}